// round 5
// baseline (speedup 1.0000x reference)
#include <cuda_runtime.h>
#include <float.h>
#include <math.h>

// MIClassifier: x[200000,768] -> attention scores -> sparsemax over N -> weighted pool -> sigmoid.
// Passes:
//   1. scores_k : scores[i] = x[i]·w_att + b_att  (streams all of x, HBM-bound) + global max
//   2. collect_k: gather all scores > z_max - 1 (sparsemax support must lie here; ~30 elems)
//   3. final_k  : single block: bitonic-sort candidates desc, exact tau, then
//                 out = sigmoid( sum_j (z_j - tau) * (x[idx_j]·w_cls) + b_cls )
//
// Exactness of the filter: if z_(k) <= z_max - 1 then cs_k >= z_max + (k-1)z_(k),
// so 1 + k z_(k) > cs_k forces z_(k) > z_max - 1. Hence support ⊆ {z > z_max - 1}.

#define NN 200000
#define DD 768
#define CAP 4096
#define ROWS_PER_BLK 16   // 512 threads, 16 warps -> 16 rows per block

// NN is divisible by 4: 200000 = 4 * 50000 (used by vectorized collect_k).
#define NN4 (NN / 4)

__device__ float g_scores[NN];
__device__ float g_cand_val[CAP];
__device__ int   g_cand_idx[CAP];
__device__ int   g_cnt;
__device__ int   g_max;   // ordered-int encoding of running max score

// monotone float<->int encoding for atomicMax on signed int
__device__ __forceinline__ int f2o(float f) {
    int i = __float_as_int(f);
    return (i >= 0) ? i : (i ^ 0x7FFFFFFF);
}
__device__ __forceinline__ float o2f(int i) {
    return __int_as_float((i >= 0) ? i : (i ^ 0x7FFFFFFF));
}

__global__ void init_k() {
    g_cnt = 0;
    g_max = f2o(-FLT_MAX);
}

// One warp per row. 768 floats = 192 float4 = 6 float4 per lane.
// Lanes cover 512B contiguous per j-step: fully coalesced, MLP=6.
__global__ void __launch_bounds__(32 * ROWS_PER_BLK) scores_k(const float* __restrict__ x,
                                                              const float* __restrict__ w_att,
                                                              const float* __restrict__ b_att) {
    __shared__ int blkmax;
    int tid  = threadIdx.x;
    int wid  = tid >> 5;
    int lane = tid & 31;
    if (tid == 0) blkmax = f2o(-FLT_MAX);
    __syncthreads();

    int row = blockIdx.x * ROWS_PER_BLK + wid;
    if (row < NN) {
        const float4* __restrict__ xr = (const float4*)(x + (size_t)row * DD);
        const float4* __restrict__ w4 = (const float4*)w_att;
        float acc = 0.f;
#pragma unroll
        for (int j = 0; j < 6; j++) {
            float4 a = xr[lane + 32 * j];
            float4 b = w4[lane + 32 * j];   // 3 KB, L1-resident, shared by all warps
            acc = fmaf(a.x, b.x, fmaf(a.y, b.y, fmaf(a.z, b.z, fmaf(a.w, b.w, acc))));
        }
#pragma unroll
        for (int o = 16; o > 0; o >>= 1) acc += __shfl_down_sync(0xFFFFFFFFu, acc, o);
        if (lane == 0) {
            float s = acc + b_att[0];
            g_scores[row] = s;
            atomicMax(&blkmax, f2o(s));     // smem atomic, cheap
        }
    }
    __syncthreads();
    if (tid == 0) atomicMax(&g_max, blkmax); // one global atomic per block
}

// Vectorized filter: float4 over the L2-resident score buffer (200000 % 4 == 0).
__global__ void __launch_bounds__(256) collect_k() {
    int i = blockIdx.x * blockDim.x + threadIdx.x;
    if (i >= NN4) return;
    float thr = o2f(g_max) - 1.0f;   // tau >= z_max - 1, so support ⊆ {z > thr}
    float4 z = ((const float4*)g_scores)[i];
    int base = i * 4;
    if (z.x > thr) { int p = atomicAdd(&g_cnt, 1); if (p < CAP) { g_cand_val[p] = z.x; g_cand_idx[p] = base + 0; } }
    if (z.y > thr) { int p = atomicAdd(&g_cnt, 1); if (p < CAP) { g_cand_val[p] = z.y; g_cand_idx[p] = base + 1; } }
    if (z.z > thr) { int p = atomicAdd(&g_cnt, 1); if (p < CAP) { g_cand_val[p] = z.z; g_cand_idx[p] = base + 2; } }
    if (z.w > thr) { int p = atomicAdd(&g_cnt, 1); if (p < CAP) { g_cand_val[p] = z.w; g_cand_idx[p] = base + 3; } }
}

__global__ void __launch_bounds__(1024) final_k(const float* __restrict__ x,
                                                const float* __restrict__ w_cls,
                                                const float* __restrict__ b_cls,
                                                float* __restrict__ out) {
    __shared__ float sval[CAP];
    __shared__ int   sidx[CAP];
    __shared__ float red[1024];
    __shared__ float s_tau;
    __shared__ int   s_kstar;

    int tid = threadIdx.x;
    int M = g_cnt;
    if (M > CAP) M = CAP;

    for (int i = tid; i < CAP; i += 1024) {
        if (i < M) { sval[i] = g_cand_val[i]; sidx[i] = g_cand_idx[i]; }
        else       { sval[i] = -FLT_MAX;      sidx[i] = 0; }
    }
    __syncthreads();

    // Bitonic sort ascending on (val, idx) pairs. Pad=-FLT_MAX sinks to the front,
    // so descending order is read from the top: z_desc[k] = sval[CAP-1-k].
    for (int k = 2; k <= CAP; k <<= 1) {
        for (int j = k >> 1; j > 0; j >>= 1) {
            for (int i = tid; i < CAP; i += 1024) {
                int ixj = i ^ j;
                if (ixj > i) {
                    bool up = ((i & k) == 0);
                    float a = sval[i], b = sval[ixj];
                    if ((a > b) == up) {
                        sval[i] = b; sval[ixj] = a;
                        int ta = sidx[i]; sidx[i] = sidx[ixj]; sidx[ixj] = ta;
                    }
                }
            }
            __syncthreads();
        }
    }

    // Exact sparsemax threshold from sorted-descending candidates.
    // support condition: 1 + k*z_(k) > cs_k  (prefix property => last true k is k*)
    if (tid == 0) {
        float cs = 0.f, css = 1.f;
        int kstar = 1;
        for (int k = 1; k <= M; k++) {
            float zk = sval[CAP - k];
            cs += zk;
            if (1.0f + (float)k * zk > cs) { kstar = k; css = cs; }
        }
        s_tau = (css - 1.0f) / (float)kstar;
        s_kstar = kstar;
    }
    __syncthreads();

    float tau = s_tau;
    int kstar = s_kstar;

    // out = sigmoid( sum_{j in support} (z_j - tau) * (x[idx_j] · w_cls) + b_cls )
    float acc = 0.f;
    for (int j = 0; j < kstar; j++) {
        float w = sval[CAP - 1 - j] - tau;
        const float* __restrict__ xr = x + (size_t)sidx[CAP - 1 - j] * DD;
        for (int d = tid; d < DD; d += 1024)
            acc = fmaf(w * xr[d], w_cls[d], acc);
    }
    red[tid] = acc;
    __syncthreads();
    for (int o = 512; o > 0; o >>= 1) {
        if (tid < o) red[tid] += red[tid + o];
        __syncthreads();
    }
    if (tid == 0) {
        float r = red[0] + b_cls[0];
        out[0] = 1.0f / (1.0f + expf(-r));
    }
}

extern "C" void kernel_launch(void* const* d_in, const int* in_sizes, int n_in,
                              void* d_out, int out_size) {
    const float* x     = (const float*)d_in[0];
    const float* w_att = (const float*)d_in[1];
    const float* b_att = (const float*)d_in[2];
    const float* w_cls = (const float*)d_in[3];
    const float* b_cls = (const float*)d_in[4];
    float* out = (float*)d_out;

    init_k<<<1, 1>>>();
    scores_k<<<(NN + ROWS_PER_BLK - 1) / ROWS_PER_BLK, 32 * ROWS_PER_BLK>>>(x, w_att, b_att);
    collect_k<<<(NN4 + 255) / 256, 256>>>();
    final_k<<<1, 1024>>>(x, w_cls, b_cls, out);
}

// round 8
// speedup vs baseline: 1.4055x; 1.4055x over previous
#include <cuda_runtime.h>
#include <float.h>
#include <math.h>

// MIClassifier: x[200000,768] -> attention scores -> sparsemax over N -> weighted pool -> sigmoid.
// Passes:
//   1. scores_k : scores[i] = x[i]·w_att + b_att  (streams all of x, HBM-bound) + global max
//   2. collect_k: gather all scores > z_max - 1 (sparsemax support must lie here; ~30 elems)
//   3. final_k  : single block: Michelot fixed-point for exact tau (NO sort), then
//                 out = sigmoid( sum_j max(z_j - tau, 0) * (x[idx_j]·w_cls) + b_cls )
//
// Filter exactness: if z_(k) <= z_max - 1 then cs_k >= z_max + (k-1)z_(k),
// so 1 + k z_(k) > cs_k forces z_(k) > z_max - 1. Hence support ⊆ {z > z_max - 1}.
// Michelot exactness: tau* is the unique fixed point of tau = (sum_{z>tau} z - 1)/|{z>tau}|;
// the pruning iteration (start all-active, drop z<=tau, recompute) reaches it in finitely
// many steps and never drops a support element (tau_iter <= tau* monotonically increasing).

#define NN 200000
#define DD 768
#define CAP 4096
#define ROWS_PER_BLK 16   // 512 threads, 16 warps -> 16 rows per block
#define NN4 (NN / 4)      // 200000 % 4 == 0
#define FT 256            // final_k threads (8 warps)

__device__ float g_scores[NN];
__device__ float g_cand_val[CAP];
__device__ int   g_cand_idx[CAP];
__device__ int   g_cnt;
__device__ int   g_max;   // ordered-int encoding of running max score

// monotone float<->int encoding for atomicMax on signed int
__device__ __forceinline__ int f2o(float f) {
    int i = __float_as_int(f);
    return (i >= 0) ? i : (i ^ 0x7FFFFFFF);
}
__device__ __forceinline__ float o2f(int i) {
    return __int_as_float((i >= 0) ? i : (i ^ 0x7FFFFFFF));
}

__global__ void init_k() {
    g_cnt = 0;
    g_max = f2o(-FLT_MAX);
}

// One warp per row. 768 floats = 192 float4 = 6 float4 per lane.
// Lanes cover 512B contiguous per j-step: fully coalesced, MLP=6. (At HBM roofline — measured.)
__global__ void __launch_bounds__(32 * ROWS_PER_BLK) scores_k(const float* __restrict__ x,
                                                              const float* __restrict__ w_att,
                                                              const float* __restrict__ b_att) {
    __shared__ int blkmax;
    int tid  = threadIdx.x;
    int wid  = tid >> 5;
    int lane = tid & 31;
    if (tid == 0) blkmax = f2o(-FLT_MAX);
    __syncthreads();

    int row = blockIdx.x * ROWS_PER_BLK + wid;
    if (row < NN) {
        const float4* __restrict__ xr = (const float4*)(x + (size_t)row * DD);
        const float4* __restrict__ w4 = (const float4*)w_att;
        float acc = 0.f;
#pragma unroll
        for (int j = 0; j < 6; j++) {
            float4 a = xr[lane + 32 * j];
            float4 b = w4[lane + 32 * j];   // 3 KB, L1-resident, shared by all warps
            acc = fmaf(a.x, b.x, fmaf(a.y, b.y, fmaf(a.z, b.z, fmaf(a.w, b.w, acc))));
        }
#pragma unroll
        for (int o = 16; o > 0; o >>= 1) acc += __shfl_down_sync(0xFFFFFFFFu, acc, o);
        if (lane == 0) {
            float s = acc + b_att[0];
            g_scores[row] = s;
            atomicMax(&blkmax, f2o(s));     // smem atomic, cheap
        }
    }
    __syncthreads();
    if (tid == 0) atomicMax(&g_max, blkmax); // one global atomic per block
}

// Vectorized filter: float4 over the L2-resident score buffer.
__global__ void __launch_bounds__(256) collect_k() {
    int i = blockIdx.x * blockDim.x + threadIdx.x;
    if (i >= NN4) return;
    float thr = o2f(g_max) - 1.0f;   // tau >= z_max - 1, so support ⊆ {z > thr}
    float4 z = ((const float4*)g_scores)[i];
    int base = i * 4;
    if (z.x > thr) { int p = atomicAdd(&g_cnt, 1); if (p < CAP) { g_cand_val[p] = z.x; g_cand_idx[p] = base + 0; } }
    if (z.y > thr) { int p = atomicAdd(&g_cnt, 1); if (p < CAP) { g_cand_val[p] = z.y; g_cand_idx[p] = base + 1; } }
    if (z.z > thr) { int p = atomicAdd(&g_cnt, 1); if (p < CAP) { g_cand_val[p] = z.z; g_cand_idx[p] = base + 2; } }
    if (z.w > thr) { int p = atomicAdd(&g_cnt, 1); if (p < CAP) { g_cand_val[p] = z.w; g_cand_idx[p] = base + 3; } }
}

// Sort-free finale: Michelot fixed-point for tau, then gathered weighted classify-dot.
__global__ void __launch_bounds__(FT) final_k(const float* __restrict__ x,
                                              const float* __restrict__ w_cls,
                                              const float* __restrict__ b_cls,
                                              float* __restrict__ out) {
    __shared__ float sval[CAP];
    __shared__ int   sidx[CAP];
    __shared__ unsigned char sact[CAP];
    __shared__ float s_psum[FT / 32];
    __shared__ int   s_pcnt[FT / 32];
    __shared__ int   s_pchg[FT / 32];
    __shared__ float s_tau;
    __shared__ int   s_stop;
    __shared__ float s_wsum[FT / 32];

    int tid  = threadIdx.x;
    int wid  = tid >> 5;
    int lane = tid & 31;
    int M = g_cnt;
    if (M > CAP) M = CAP;

    for (int i = tid; i < M; i += FT) {
        sval[i] = g_cand_val[i];
        sidx[i] = g_cand_idx[i];
        sact[i] = 1;
    }
    if (tid == 0) s_stop = 0;
    __syncthreads();

    // Michelot iteration: tau = (sum_active - 1)/cnt_active; drop z <= tau; repeat.
    // Converges exactly in finitely many rounds (typically 3-5 for M ~ 30).
    while (true) {
        float ls = 0.f;
        int   lc = 0;
        for (int i = tid; i < M; i += FT)
            if (sact[i]) { ls += sval[i]; lc++; }
#pragma unroll
        for (int o = 16; o > 0; o >>= 1) {
            ls += __shfl_down_sync(0xFFFFFFFFu, ls, o);
            lc += __shfl_down_sync(0xFFFFFFFFu, lc, o);
        }
        if (lane == 0) { s_psum[wid] = ls; s_pcnt[wid] = lc; }
        __syncthreads();
        if (tid == 0) {
            float sum = 0.f; int cnt = 0;
#pragma unroll
            for (int w = 0; w < FT / 32; w++) { sum += s_psum[w]; cnt += s_pcnt[w]; }
            s_tau = (sum - 1.0f) / (float)cnt;   // cnt >= 1 always (z_max stays active)
        }
        __syncthreads();

        float tau = s_tau;
        int chg = 0;
        for (int i = tid; i < M; i += FT)
            if (sact[i] && sval[i] <= tau) { sact[i] = 0; chg = 1; }
#pragma unroll
        for (int o = 16; o > 0; o >>= 1) chg |= __shfl_down_sync(0xFFFFFFFFu, chg, o);
        if (lane == 0) s_pchg[wid] = chg;
        __syncthreads();
        if (tid == 0) {
            int any = 0;
#pragma unroll
            for (int w = 0; w < FT / 32; w++) any |= s_pchg[w];
            s_stop = !any;
        }
        __syncthreads();
        if (s_stop) break;
    }

    float tau = s_tau;

    // out = sigmoid( sum_j max(z_j - tau, 0) * (x[idx_j] · w_cls) + b_cls )
    // One warp per candidate row; lanes cover 768 floats as 6 float4 each.
    float acc = 0.f;
    for (int j = wid; j < M; j += FT / 32) {
        float w = sval[j] - tau;
        if (w <= 0.f) continue;                    // pruned candidate
        const float4* __restrict__ xr = (const float4*)(x + (size_t)sidx[j] * DD);
        const float4* __restrict__ c4 = (const float4*)w_cls;
        float d = 0.f;
#pragma unroll
        for (int q = 0; q < 6; q++) {
            float4 a = xr[lane + 32 * q];
            float4 b = c4[lane + 32 * q];
            d = fmaf(a.x, b.x, fmaf(a.y, b.y, fmaf(a.z, b.z, fmaf(a.w, b.w, d))));
        }
        acc = fmaf(w, d, acc);
    }
#pragma unroll
    for (int o = 16; o > 0; o >>= 1) acc += __shfl_down_sync(0xFFFFFFFFu, acc, o);
    if (lane == 0) s_wsum[wid] = acc;
    __syncthreads();
    if (tid == 0) {
        float r = 0.f;
#pragma unroll
        for (int w = 0; w < FT / 32; w++) r += s_wsum[w];  // fixed order: deterministic
        r += b_cls[0];
        out[0] = 1.0f / (1.0f + expf(-r));
    }
}

extern "C" void kernel_launch(void* const* d_in, const int* in_sizes, int n_in,
                              void* d_out, int out_size) {
    const float* x     = (const float*)d_in[0];
    const float* w_att = (const float*)d_in[1];
    const float* b_att = (const float*)d_in[2];
    const float* w_cls = (const float*)d_in[3];
    const float* b_cls = (const float*)d_in[4];
    float* out = (float*)d_out;

    init_k<<<1, 1>>>();
    scores_k<<<(NN + ROWS_PER_BLK - 1) / ROWS_PER_BLK, 32 * ROWS_PER_BLK>>>(x, w_att, b_att);
    collect_k<<<(NN4 + 255) / 256, 256>>>();
    final_k<<<1, FT>>>(x, w_cls, b_cls, out);
}

// round 11
// speedup vs baseline: 1.4388x; 1.0238x over previous
#include <cuda_runtime.h>
#include <float.h>
#include <math.h>

// MIClassifier: x[200000,768] -> attention scores -> sparsemax over N -> weighted pool -> sigmoid.
// Passes:
//   1. scores_k : scores[i] = x[i]·w_att + b_att  (streams all of x, HBM-bound) + global max
//   2. collect_k: gather all scores > z_max - 1 (sparsemax support must lie here; ~30 elems)
//   3. final_k  : dots d_j = x[idx_j]·w_cls first (warp-per-row, max MLP), then warp-0
//                 register Michelot for exact tau, then sigmoid(sum max(z_j-tau,0)*d_j + b).
//
// Filter exactness: if z_(k) <= z_max - 1 then cs_k >= z_max + (k-1)z_(k),
// so 1 + k z_(k) > cs_k forces z_(k) > z_max - 1. Hence support ⊆ {z > z_max - 1}.
// Michelot exactness: tau* is the unique fixed point of tau = (sum_{z>tau} z - 1)/|{z>tau}|;
// pruning iteration (all-active start, drop z<=tau, recompute) reaches it finitely and
// never drops a support element.

#define NN 200000
#define DD 768
#define CAP 4096
#define ROWS_PER_BLK 16   // 512 threads, 16 warps -> 16 rows per block
#define NN4 (NN / 4)      // 200000 % 4 == 0
#define FT 1024           // final_k threads (32 warps: one warp per candidate row)

__device__ float g_scores[NN];
__device__ float g_cand_val[CAP];
__device__ int   g_cand_idx[CAP];
__device__ int   g_cnt;
__device__ int   g_max;   // ordered-int encoding of running max score

__device__ __forceinline__ int f2o(float f) {
    int i = __float_as_int(f);
    return (i >= 0) ? i : (i ^ 0x7FFFFFFF);
}
__device__ __forceinline__ float o2f(int i) {
    return __int_as_float((i >= 0) ? i : (i ^ 0x7FFFFFFF));
}

__global__ void init_k() {
    g_cnt = 0;
    g_max = f2o(-FLT_MAX);
}

// One warp per row. 768 floats = 192 float4 = 6 float4 per lane, 512B contiguous/step.
// __ldcs: x is 614MB single-use -> evict-first, keep L2 for the scores buffer.
__global__ void __launch_bounds__(32 * ROWS_PER_BLK) scores_k(const float* __restrict__ x,
                                                              const float* __restrict__ w_att,
                                                              const float* __restrict__ b_att) {
    __shared__ int blkmax;
    int tid  = threadIdx.x;
    int wid  = tid >> 5;
    int lane = tid & 31;
    if (tid == 0) blkmax = f2o(-FLT_MAX);
    __syncthreads();

    int row = blockIdx.x * ROWS_PER_BLK + wid;
    if (row < NN) {
        const float4* __restrict__ xr = (const float4*)(x + (size_t)row * DD);
        const float4* __restrict__ w4 = (const float4*)w_att;
        float acc = 0.f;
#pragma unroll
        for (int j = 0; j < 6; j++) {
            float4 a = __ldcs(xr + lane + 32 * j);
            float4 b = w4[lane + 32 * j];   // 3 KB, L1-resident, shared by all warps
            acc = fmaf(a.x, b.x, fmaf(a.y, b.y, fmaf(a.z, b.z, fmaf(a.w, b.w, acc))));
        }
#pragma unroll
        for (int o = 16; o > 0; o >>= 1) acc += __shfl_down_sync(0xFFFFFFFFu, acc, o);
        if (lane == 0) {
            float s = acc + b_att[0];
            g_scores[row] = s;
            atomicMax(&blkmax, f2o(s));
        }
    }
    __syncthreads();
    if (tid == 0) atomicMax(&g_max, blkmax);
}

// Vectorized filter: float4 over the L2-resident score buffer.
__global__ void __launch_bounds__(256) collect_k() {
    int i = blockIdx.x * blockDim.x + threadIdx.x;
    if (i >= NN4) return;
    float thr = o2f(g_max) - 1.0f;   // tau >= z_max - 1, so support ⊆ {z > thr}
    float4 z = ((const float4*)g_scores)[i];
    int base = i * 4;
    if (z.x > thr) { int p = atomicAdd(&g_cnt, 1); if (p < CAP) { g_cand_val[p] = z.x; g_cand_idx[p] = base + 0; } }
    if (z.y > thr) { int p = atomicAdd(&g_cnt, 1); if (p < CAP) { g_cand_val[p] = z.y; g_cand_idx[p] = base + 1; } }
    if (z.z > thr) { int p = atomicAdd(&g_cnt, 1); if (p < CAP) { g_cand_val[p] = z.z; g_cand_idx[p] = base + 2; } }
    if (z.w > thr) { int p = atomicAdd(&g_cnt, 1); if (p < CAP) { g_cand_val[p] = z.w; g_cand_idx[p] = base + 3; } }
}

// Latency-optimized finale:
//   phase A (all 32 warps): d_j = x[idx_j]·w_cls, one warp per row -> all gathers in flight
//   phase B (warp 0 only) : Michelot tau via butterfly shuffles, zero block barriers
//   phase C (warp 0)      : r = sum max(z_j - tau, 0) * d_j + b; out = sigmoid(r)
__global__ void __launch_bounds__(FT) final_k(const float* __restrict__ x,
                                              const float* __restrict__ w_cls,
                                              const float* __restrict__ b_cls,
                                              float* __restrict__ out) {
    __shared__ float sval[CAP];
    __shared__ int   sidx[CAP];
    __shared__ float sd[CAP];
    __shared__ unsigned char sact[CAP];

    int tid  = threadIdx.x;
    int wid  = tid >> 5;
    int lane = tid & 31;
    int M = g_cnt;
    if (M > CAP) M = CAP;

    for (int i = tid; i < M; i += FT) {
        sval[i] = g_cand_val[i];
        sidx[i] = g_cand_idx[i];
    }
    __syncthreads();

    // Phase A: per-candidate classify-dots (tau-independent). One warp per row.
    for (int j = wid; j < M; j += FT / 32) {
        const float4* __restrict__ xr = (const float4*)(x + (size_t)sidx[j] * DD);
        const float4* __restrict__ c4 = (const float4*)w_cls;
        float d = 0.f;
#pragma unroll
        for (int q = 0; q < 6; q++) {
            float4 a = xr[lane + 32 * q];
            float4 b = c4[lane + 32 * q];
            d = fmaf(a.x, b.x, fmaf(a.y, b.y, fmaf(a.z, b.z, fmaf(a.w, b.w, d))));
        }
#pragma unroll
        for (int o = 16; o > 0; o >>= 1) d += __shfl_down_sync(0xFFFFFFFFu, d, o);
        if (lane == 0) sd[j] = d;
    }
    __syncthreads();

    // Phases B+C: warp 0 only; each lane owns items i = lane, lane+32, ...
    // (distinct smem slots per lane -> no races; all cross-lane comm via shuffles)
    if (wid == 0) {
        for (int i = lane; i < M; i += 32) sact[i] = 1;
        float tau;
        while (true) {
            float ls = 0.f;
            int   lc = 0;
            for (int i = lane; i < M; i += 32)
                if (sact[i]) { ls += sval[i]; lc++; }
#pragma unroll
            for (int o = 16; o > 0; o >>= 1) {
                ls += __shfl_xor_sync(0xFFFFFFFFu, ls, o);
                lc += __shfl_xor_sync(0xFFFFFFFFu, lc, o);
            }
            tau = (ls - 1.0f) / (float)lc;   // lc >= 1 (z_max always active)
            int chg = 0;
            for (int i = lane; i < M; i += 32)
                if (sact[i] && sval[i] <= tau) { sact[i] = 0; chg = 1; }
            if (!__any_sync(0xFFFFFFFFu, chg)) break;
        }

        float acc = 0.f;
        for (int i = lane; i < M; i += 32) {
            float w = sval[i] - tau;
            if (w > 0.f) acc = fmaf(w, sd[i], acc);
        }
#pragma unroll
        for (int o = 16; o > 0; o >>= 1) acc += __shfl_xor_sync(0xFFFFFFFFu, acc, o);
        if (lane == 0) {
            float r = acc + b_cls[0];
            out[0] = 1.0f / (1.0f + expf(-r));
        }
    }
}

extern "C" void kernel_launch(void* const* d_in, const int* in_sizes, int n_in,
                              void* d_out, int out_size) {
    const float* x     = (const float*)d_in[0];
    const float* w_att = (const float*)d_in[1];
    const float* b_att = (const float*)d_in[2];
    const float* w_cls = (const float*)d_in[3];
    const float* b_cls = (const float*)d_in[4];
    float* out = (float*)d_out;

    init_k<<<1, 1>>>();
    scores_k<<<(NN + ROWS_PER_BLK - 1) / ROWS_PER_BLK, 32 * ROWS_PER_BLK>>>(x, w_att, b_att);
    collect_k<<<(NN4 + 255) / 256, 256>>>();
    final_k<<<1, FT>>>(x, w_cls, b_cls, out);
}